// round 15
// baseline (speedup 1.0000x reference)
#include <cuda_runtime.h>
#include <cuda_fp16.h>
#include <cstdint>

// Problem constants (fixed by reference: B=4, S=2048, D=1024, H=16)
#define DD     1024
#define NH     16
#define HD     64
#define BATCH  4
#define SEQ    2048
#define MTOT   (BATCH * SEQ)      // 8192
#define CHUNK  64
#define NCHUNK (SEQ / CHUNK)      // 32
#define NBH    (BATCH * NH)       // 64
#define LDT    72                 // smem halves per tile row (64 + 8 pad)

// ---------------- scratch (allocation-free rule: __device__ globals) -------
__device__ __half g_KVh[NBH * NCHUNK * HD * HD];   // chunk KV -> exclusive prefix (fp16)
__device__ float  g_KS [NBH * NCHUNK * HD];

__device__ __half g_xh  [MTOT * DD];     // x in fp16
__device__ __half g_qh  [MTOT * DD];     // phi(xWq+b)
__device__ __half g_kh  [MTOT * DD];     // phi(xWk+b)
__device__ __half g_vh  [MTOT * DD];     // xWv+b
__device__ __half g_valh[MTOT * DD];     // attention output (fp16)
__device__ __half g_wT  [4][DD * DD];    // W^T fp16 (layout [N][K])

// ---------------------------------------------------------------------------
// PTX helpers (compute_100-safe: mma.sync / ldmatrix / cp.async only)
// ---------------------------------------------------------------------------
__device__ __forceinline__ uint32_t smem_u32(const void* p) {
    uint32_t a;
    asm("{ .reg .u64 t; cvta.to.shared.u64 t, %1; cvt.u32.u64 %0, t; }" : "=r"(a) : "l"(p));
    return a;
}

#define CP_ASYNC16(dst_u32, src_gptr) \
    asm volatile("cp.async.cg.shared.global [%0], [%1], 16;" \
                 :: "r"(dst_u32), "l"(src_gptr) : "memory")
#define CP_COMMIT() asm volatile("cp.async.commit_group;" ::: "memory")
#define CP_WAIT(n)  asm volatile("cp.async.wait_group %0;" :: "n"(n) : "memory")

#define LDSM_X4(r0, r1, r2, r3, addr) \
    asm volatile("ldmatrix.sync.aligned.m8n8.x4.shared.b16 {%0,%1,%2,%3}, [%4];" \
                 : "=r"(r0), "=r"(r1), "=r"(r2), "=r"(r3) : "r"(addr))

#define LDSM_X4_T(r0, r1, r2, r3, addr) \
    asm volatile("ldmatrix.sync.aligned.m8n8.x4.trans.shared.b16 {%0,%1,%2,%3}, [%4];" \
                 : "=r"(r0), "=r"(r1), "=r"(r2), "=r"(r3) : "r"(addr))

#define MMA16816F16(d, a, b0v, b1v) \
    asm volatile("mma.sync.aligned.m16n8k16.row.col.f32.f16.f16.f32 " \
                 "{%0,%1,%2,%3}, {%4,%5,%6,%7}, {%8,%9}, {%0,%1,%2,%3};" \
                 : "+f"((d)[0]), "+f"((d)[1]), "+f"((d)[2]), "+f"((d)[3]) \
                 : "r"((a)[0]), "r"((a)[1]), "r"((a)[2]), "r"((a)[3]), \
                   "r"(b0v), "r"(b1v))

__device__ __forceinline__ uint32_t packh2(float x, float y) {
    __half2 h = __floats2half2_rn(x, y);
    return *(uint32_t*)&h;
}

// ---------------------------------------------------------------------------
// Merged conversion kernel: blocks [0, NCVH) do x fp32->fp16; the rest do the
// four weight transposes+converts. One launch, both parts run concurrently.
// ---------------------------------------------------------------------------
#define NCVH 1184
__global__ __launch_bounds__(256)
void conv_all_k(const float4* __restrict__ x, uint4* __restrict__ xh, int n8,
                const float* __restrict__ W0, const float* __restrict__ W1,
                const float* __restrict__ W2, const float* __restrict__ W3,
                __half* __restrict__ hTbase)
{
    __shared__ float t[32][33];
    const int tid = threadIdx.x;
    if (blockIdx.x < NCVH) {
        for (int i = blockIdx.x * 256 + tid; i < n8; i += NCVH * 256) {
            float4 a = x[2 * i];
            float4 b = x[2 * i + 1];
            uint4 o;
            o.x = packh2(a.x, a.y);
            o.y = packh2(a.z, a.w);
            o.z = packh2(b.x, b.y);
            o.w = packh2(b.z, b.w);
            xh[i] = o;
        }
    } else {
        const int bidx = blockIdx.x - NCVH;        // 0..4095
        const int z = bidx >> 10;
        const int rem = bidx & 1023;
        const int n0 = (rem & 31) * 32, k0 = (rem >> 5) * 32;
        const float* W = (z == 0) ? W0 : (z == 1) ? W1 : (z == 2) ? W2 : W3;
        __half* hT = hTbase + (size_t)z * DD * DD;
        const int tx = tid & 31, ty = tid >> 5;    // 32 x 8
        #pragma unroll
        for (int r = ty; r < 32; r += 8)
            t[r][tx] = W[(size_t)(k0 + r) * DD + n0 + tx];
        __syncthreads();
        #pragma unroll
        for (int r = ty; r < 32; r += 8)
            hT[(size_t)(n0 + r) * DD + k0 + tx] = __float2half_rn(t[tx][r]);
    }
}

// ---------------------------------------------------------------------------
// fp16 tensor-core GEMM mainloop body
// CTA tile TM x 128, BK=32, 8 warps, 3-stage cp.async, single barrier/iter.
// TM=64: warp tile 32x32 (MF=2).  TM=32: warp tile 16x32 (MF=1).
// ---------------------------------------------------------------------------
template<int HALF_OUT, int TM>
__device__ __forceinline__
void gemm_body(int tid, uint32_t sb, uint64_t gA, uint64_t gB,
               int m0, int n0, bool act, const float* bias, void* Cg)
{
    constexpr int SROWB  = 80;
    constexpr int ATILEB = TM * SROWB;
    constexpr int BTILEB = 128 * SROWB;
    constexpr int STAGEB = ATILEB + BTILEB;
    constexpr int NIT    = DD / 32;
    constexpr int MF     = TM / 32;          // m16-fragments per warp

    const int lane = tid & 31;
    const int wid = tid >> 5;
    const int wm = wid & 1;                  // M half
    const int wn = wid >> 1;                 // 32-col slab
    const uint32_t aOff = (uint32_t)(wm * (TM / 2) + (lane & 15)) * SROWB
                        + (uint32_t)(lane >> 4) * 16;
    const uint32_t bOff = (uint32_t)(wn * 32 + (lane & 7) + ((lane >> 4) << 3)) * SROWB
                        + (uint32_t)((lane >> 3) & 1) * 16;

    float acc[MF][4][4];
    #pragma unroll
    for (int i = 0; i < MF; i++)
        #pragma unroll
        for (int j = 0; j < 4; j++)
            #pragma unroll
            for (int q = 0; q < 4; q++) acc[i][j][q] = 0.f;

    auto load_stage = [&](int slot, int kc) {
        const uint32_t sbase = sb + slot * STAGEB;
        #pragma unroll
        for (int idx = tid; idx < TM * 4; idx += 256) {  // A: TM rows x 4 chunks
            const int row = idx >> 2, k = idx & 3;
            CP_ASYNC16(sbase + row * SROWB + k * 16,
                       gA + ((size_t)(m0 + row) * DD + kc + k * 8) * 2);
        }
        #pragma unroll
        for (int idx = tid; idx < 512; idx += 256) {     // B: 128 rows x 4 chunks
            const int row = idx >> 2, k = idx & 3;
            CP_ASYNC16(sbase + ATILEB + row * SROWB + k * 16,
                       gB + ((size_t)(n0 + row) * DD + kc + k * 8) * 2);
        }
    };

    load_stage(0, 0);  CP_COMMIT();
    load_stage(1, 32); CP_COMMIT();

    for (int it = 0; it < NIT; it++) {
        if (it + 1 < NIT) { CP_WAIT(1); } else { CP_WAIT(0); }
        __syncthreads();
        if (it + 2 < NIT) { load_stage((it + 2) % 3, (it + 2) * 32); CP_COMMIT(); }

        const int slot = it % 3;
        const uint32_t sA = sb + slot * STAGEB;
        const uint32_t sB = sA + ATILEB;

        #pragma unroll
        for (int k16 = 0; k16 < 2; k16++) {
            const uint32_t kb = k16 * 32;
            uint32_t ah[MF][4];
            #pragma unroll
            for (int mf = 0; mf < MF; mf++) {
                const uint32_t ao = aOff + mf * 16 * SROWB + kb;
                LDSM_X4(ah[mf][0], ah[mf][1], ah[mf][2], ah[mf][3], sA + ao);
            }
            uint32_t bb[2][4];
            #pragma unroll
            for (int gg = 0; gg < 2; gg++) {
                const uint32_t bo = bOff + gg * 16 * SROWB + kb;
                LDSM_X4(bb[gg][0], bb[gg][1], bb[gg][2], bb[gg][3], sB + bo);
            }
            #pragma unroll
            for (int mf = 0; mf < MF; mf++) {
                #pragma unroll
                for (int nf = 0; nf < 4; nf++) {
                    const int gg = nf >> 1, p = (nf & 1) * 2;
                    MMA16816F16(acc[mf][nf], ah[mf], bb[gg][p], bb[gg][p + 1]);
                }
            }
        }
    }

    #pragma unroll
    for (int nf = 0; nf < 4; nf++) {
        const int cg = n0 + wn * 32 + nf * 8 + (lane & 3) * 2;
        const float b0 = __ldg(&bias[cg]);
        const float b1 = __ldg(&bias[cg + 1]);
        #pragma unroll
        for (int mf = 0; mf < MF; mf++) {
            const int rg = m0 + wm * (TM / 2) + mf * 16 + (lane >> 2);
            float v0 = acc[mf][nf][0] + b0;
            float v1 = acc[mf][nf][1] + b1;
            float v2 = acc[mf][nf][2] + b0;
            float v3 = acc[mf][nf][3] + b1;
            if (act) {
                v0 = (v0 > 0.f) ? (v0 + 1.f) : __expf(v0);
                v1 = (v1 > 0.f) ? (v1 + 1.f) : __expf(v1);
                v2 = (v2 > 0.f) ? (v2 + 1.f) : __expf(v2);
                v3 = (v3 > 0.f) ? (v3 + 1.f) : __expf(v3);
            }
            if (HALF_OUT) {
                __half* Ch = (__half*)Cg;
                *(__half2*)(Ch + (size_t)rg * DD + cg)       = __floats2half2_rn(v0, v1);
                *(__half2*)(Ch + (size_t)(rg + 8) * DD + cg) = __floats2half2_rn(v2, v3);
            } else {
                float* Cf = (float*)Cg;
                *(float2*)(Cf + (size_t)rg * DD + cg)       = make_float2(v0, v1);
                *(float2*)(Cf + (size_t)(rg + 8) * DD + cg) = make_float2(v2, v3);
            }
        }
    }
}

#define GTM 64    // qkv GEMM M-tile
#define OTM 32    // output-projection M-tile (smaller -> less wave quantization)

// Fused Q/K/V projections: grid.x = 3*8 (which*8 + nblk), grid.y = MTOT/GTM
__global__ __launch_bounds__(256, 3)
void qkv_gemm_k(const __half* __restrict__ A, const __half* __restrict__ wT,
                const float* __restrict__ bq, const float* __restrict__ bk,
                const float* __restrict__ bv)
{
    extern __shared__ char smem[];
    const int which = blockIdx.x >> 3;
    const int n0 = (blockIdx.x & 7) * 128;
    const int m0 = blockIdx.y * GTM;
    const __half* BT = wT + (size_t)which * DD * DD;
    const float* bias = (which == 0) ? bq : (which == 1) ? bk : bv;
    __half* out = (which == 0) ? g_qh : (which == 1) ? g_kh : g_vh;
    gemm_body<1, GTM>(threadIdx.x, smem_u32(smem), __cvta_generic_to_global(A),
                      __cvta_generic_to_global(BT), m0, n0, which < 2, bias, out);
}

// Output projection: fp16 A, fp32 C; TM=32 tiles, 4 CTAs/SM
__global__ __launch_bounds__(256, 4)
void out_gemm_k(const __half* __restrict__ A, const __half* __restrict__ BT,
                const float* __restrict__ bias, float* __restrict__ Cg)
{
    extern __shared__ char smem[];
    gemm_body<0, OTM>(threadIdx.x, smem_u32(smem), __cvta_generic_to_global(A),
                      __cvta_generic_to_global(BT), blockIdx.y * OTM,
                      blockIdx.x * 128, false, bias, Cg);
}

// ---------------------------------------------------------------------------
// Async tile loaders: 64x64 fp16 -> smem [64][LDT] via cp.async
// ---------------------------------------------------------------------------
__device__ __forceinline__
void load_tile_cp(uint32_t dst_s, const __half* src, size_t rowbase, int tid)
{
    #pragma unroll
    for (int j = 0; j < 4; j++) {
        const int idx = tid + 128 * j;
        const int row = idx >> 3;
        const int c = (idx & 7) * 8;
        CP_ASYNC16(dst_s + (uint32_t)(row * LDT + c) * 2,
                   (const void*)(src + rowbase + (size_t)row * DD + c));
    }
}
__device__ __forceinline__
void load_tile_cp_s(uint32_t dst_s, const __half* src, int tid)
{
    #pragma unroll
    for (int j = 0; j < 4; j++) {
        const int idx = tid + 128 * j;
        const int row = idx >> 3;
        const int c = (idx & 7) * 8;
        CP_ASYNC16(dst_s + (uint32_t)(row * LDT + c) * 2,
                   (const void*)(src + (size_t)row * HD + c));
    }
}

// ---------------------------------------------------------------------------
// Pass A (tensor core): KV_c[d][m] = sum_t K[t][d] V[t][m] (fp16 out);
// ks_c[d] = sum_t K[t][d] (fp32)
// ---------------------------------------------------------------------------
__global__ __launch_bounds__(128)
void kv_chunk_tc()
{
    __shared__ __half Ks[CHUNK][LDT];
    __shared__ __half Vs[CHUNK][LDT];

    const int c = blockIdx.x, bh = blockIdx.y;
    const int b = bh >> 4, h = bh & 15;
    const int tid = threadIdx.x;
    const int w = tid >> 5, l = tid & 31;
    const size_t rowbase = (size_t)(b * SEQ + c * CHUNK) * DD + h * HD;

    load_tile_cp(smem_u32(Ks), g_kh, rowbase, tid);
    load_tile_cp(smem_u32(Vs), g_vh, rowbase, tid);
    CP_COMMIT();
    CP_WAIT(0);
    __syncthreads();

    const int tRow = ((l >> 4) << 3) + (l & 7);
    const int tColA = ((l >> 3) & 1) * 8;
    const int tRowB = ((l >> 3) & 1) * 8 + (l & 7);
    const int tColB = (l >> 4) * 8;

    float acc[8][4];
    #pragma unroll
    for (int i = 0; i < 8; i++)
        #pragma unroll
        for (int q = 0; q < 4; q++) acc[i][q] = 0.f;

    #pragma unroll
    for (int kk = 0; kk < 4; kk++) {
        uint32_t a[4];
        LDSM_X4_T(a[0], a[1], a[2], a[3],
                  smem_u32(&Ks[kk * 16 + tRow][w * 16 + tColA]));
        #pragma unroll
        for (int gN = 0; gN < 4; gN++) {
            uint32_t r0, r1, r2, r3;
            LDSM_X4_T(r0, r1, r2, r3,
                      smem_u32(&Vs[kk * 16 + tRowB][gN * 16 + tColB]));
            MMA16816F16(acc[2 * gN],     a, r0, r1);
            MMA16816F16(acc[2 * gN + 1], a, r2, r3);
        }
    }

    __half* outp = g_KVh + (size_t)(bh * NCHUNK + c) * HD * HD;
    const int r0 = w * 16 + (l >> 2);
    #pragma unroll
    for (int nf = 0; nf < 8; nf++) {
        const int col = nf * 8 + 2 * (l & 3);
        *(uint32_t*)(outp + (size_t)r0 * HD + col)       = packh2(acc[nf][0], acc[nf][1]);
        *(uint32_t*)(outp + (size_t)(r0 + 8) * HD + col) = packh2(acc[nf][2], acc[nf][3]);
    }

    if (tid < HD) {
        float s = 0.f;
        #pragma unroll 8
        for (int t = 0; t < CHUNK; t++) s += __half2float(Ks[t][tid]);
        g_KS[(bh * NCHUNK + c) * HD + tid] = s;
    }
}

// ---------------------------------------------------------------------------
// Pass B: in-place EXCLUSIVE prefix over chunks. 8 CTAs per bh; each thread
// owns one half2 lane. All 32 chunk values preloaded into registers (MLP=32),
// scan in registers, then store.
// ---------------------------------------------------------------------------
__global__ __launch_bounds__(256)
void prefix_k()
{
    const int bh = blockIdx.x >> 3;
    const int pos = (blockIdx.x & 7) * 256 + threadIdx.x;   // 0..2047 half2 lanes
    __half* base = g_KVh + (size_t)bh * NCHUNK * HD * HD + pos * 2;

    uint32_t v[NCHUNK];
    #pragma unroll
    for (int c = 0; c < NCHUNK; c++)
        v[c] = *(const uint32_t*)(base + (size_t)c * HD * HD);

    float rx = 0.f, ry = 0.f;
    #pragma unroll
    for (int c = 0; c < NCHUNK; c++) {
        float2 f = __half22float2(*(__half2*)&v[c]);
        *(uint32_t*)(base + (size_t)c * HD * HD) = packh2(rx, ry);
        rx += f.x; ry += f.y;
    }

    if ((blockIdx.x & 7) == 0 && threadIdx.x < HD) {
        float* zb = g_KS + (size_t)bh * NCHUNK * HD + threadIdx.x;
        float zv[NCHUNK];
        #pragma unroll
        for (int c = 0; c < NCHUNK; c++) zv[c] = zb[(size_t)c * HD];
        float r = 0.f;
        #pragma unroll
        for (int c = 0; c < NCHUNK; c++) {
            zb[(size_t)c * HD] = r;
            r += zv[c];
        }
    }
}

// ---------------------------------------------------------------------------
// Pass C (tensor core): out = (tril(QK^T) V + Q S_prev) / (rowsum + Q.z + eps)
// K and V share one smem buffer (K dead after Phase 1) -> 28.5 KB, 8 CTAs/SM.
// ---------------------------------------------------------------------------
__global__ __launch_bounds__(128)
void attn_out_tc()
{
    __shared__ __half Qs [CHUNK][LDT];
    __shared__ __half KVs[CHUNK][LDT];     // K in Phase 1, V in Phase 2
    __shared__ __half Sph[HD][LDT];
    __shared__ float rs[CHUNK], den[CHUNK], zp[HD];

    const int c = blockIdx.x, bh = blockIdx.y;
    const int b = bh >> 4, h = bh & 15;
    const int tid = threadIdx.x;
    const int w = tid >> 5, l = tid & 31;
    const size_t rowbase = (size_t)(b * SEQ + c * CHUNK) * DD + h * HD;
    const __half* Sp = g_KVh + (size_t)(bh * NCHUNK + c) * HD * HD;

    load_tile_cp(smem_u32(Qs), g_qh, rowbase, tid);
    load_tile_cp(smem_u32(KVs), g_kh, rowbase, tid);
    load_tile_cp_s(smem_u32(Sph), Sp, tid);
    CP_COMMIT();
    if (tid < HD) zp[tid] = g_KS[(bh * NCHUNK + c) * HD + tid];
    CP_WAIT(0);
    __syncthreads();

    const uint32_t aRow = w * 16 + (l & 15);
    const uint32_t aK = (l >> 4) * 8;
    const uint32_t bRow = (l & 7) + ((l >> 4) << 3);
    const uint32_t bK = ((l >> 3) & 1) * 8;
    const int tRowB = ((l >> 3) & 1) * 8 + (l & 7);
    const int tColB = (l >> 4) * 8;

    // Phase 1: S = Q K^T
    float accS[8][4];
    #pragma unroll
    for (int i = 0; i < 8; i++)
        #pragma unroll
        for (int q = 0; q < 4; q++) accS[i][q] = 0.f;

    #pragma unroll
    for (int kk = 0; kk < 4; kk++) {
        uint32_t a[4];
        LDSM_X4(a[0], a[1], a[2], a[3], smem_u32(&Qs[aRow][kk * 16 + aK]));
        #pragma unroll
        for (int gN = 0; gN < 4; gN++) {
            uint32_t r0, r1, r2, r3;
            LDSM_X4(r0, r1, r2, r3, smem_u32(&KVs[gN * 16 + bRow][kk * 16 + bK]));
            MMA16816F16(accS[2 * gN],     a, r0, r1);
            MMA16816F16(accS[2 * gN + 1], a, r2, r3);
        }
    }

    const int row0 = w * 16 + (l >> 2);
    const int row1 = row0 + 8;
    float sum0 = 0.f, sum1 = 0.f;
    #pragma unroll
    for (int nf = 0; nf < 8; nf++) {
        #pragma unroll
        for (int jj = 0; jj < 2; jj++) {
            const int col = nf * 8 + 2 * (l & 3) + jj;
            accS[nf][jj]     = (col <= row0) ? accS[nf][jj]     : 0.f;
            accS[nf][2 + jj] = (col <= row1) ? accS[nf][2 + jj] : 0.f;
            sum0 += accS[nf][jj];
            sum1 += accS[nf][2 + jj];
        }
    }
    sum0 += __shfl_xor_sync(0xFFFFFFFF, sum0, 1);
    sum0 += __shfl_xor_sync(0xFFFFFFFF, sum0, 2);
    sum1 += __shfl_xor_sync(0xFFFFFFFF, sum1, 1);
    sum1 += __shfl_xor_sync(0xFFFFFFFF, sum1, 2);
    if ((l & 3) == 0) { rs[row0] = sum0; rs[row1] = sum1; }
    __syncthreads();   // all warps done with K reads + rs visible

    // reload KVs with V while computing denominators
    load_tile_cp(smem_u32(KVs), g_vh, rowbase, tid);
    CP_COMMIT();
    if (tid < CHUNK) {
        float qz = 0.f;
        #pragma unroll 8
        for (int d = 0; d < HD; d++) qz = fmaf(__half2float(Qs[tid][d]), zp[d], qz);
        den[tid] = rs[tid] + qz + 1e-6f;
    }
    CP_WAIT(0);
    __syncthreads();

    // Phase 2: O = S V + Q S_prev
    float accO[8][4];
    #pragma unroll
    for (int i = 0; i < 8; i++)
        #pragma unroll
        for (int q = 0; q < 4; q++) accO[i][q] = 0.f;

    #pragma unroll
    for (int kk = 0; kk < 4; kk++) {
        uint32_t a[4];
        a[0] = packh2(accS[2 * kk][0],     accS[2 * kk][1]);
        a[1] = packh2(accS[2 * kk][2],     accS[2 * kk][3]);
        a[2] = packh2(accS[2 * kk + 1][0], accS[2 * kk + 1][1]);
        a[3] = packh2(accS[2 * kk + 1][2], accS[2 * kk + 1][3]);
        #pragma unroll
        for (int gN = 0; gN < 4; gN++) {
            uint32_t r0, r1, r2, r3;
            LDSM_X4_T(r0, r1, r2, r3,
                      smem_u32(&KVs[kk * 16 + tRowB][gN * 16 + tColB]));
            MMA16816F16(accO[2 * gN],     a, r0, r1);
            MMA16816F16(accO[2 * gN + 1], a, r2, r3);
        }
    }
    #pragma unroll
    for (int kk = 0; kk < 4; kk++) {
        uint32_t a[4];
        LDSM_X4(a[0], a[1], a[2], a[3], smem_u32(&Qs[aRow][kk * 16 + aK]));
        #pragma unroll
        for (int gN = 0; gN < 4; gN++) {
            uint32_t r0, r1, r2, r3;
            LDSM_X4_T(r0, r1, r2, r3,
                      smem_u32(&Sph[kk * 16 + tRowB][gN * 16 + tColB]));
            MMA16816F16(accO[2 * gN],     a, r0, r1);
            MMA16816F16(accO[2 * gN + 1], a, r2, r3);
        }
    }

    const float inv0 = 1.0f / den[row0];
    const float inv1 = 1.0f / den[row1];
    #pragma unroll
    for (int nf = 0; nf < 8; nf++) {
        const int col = nf * 8 + 2 * (l & 3);
        *(uint32_t*)(g_valh + rowbase + (size_t)row0 * DD + col) =
            packh2(accO[nf][0] * inv0, accO[nf][1] * inv0);
        *(uint32_t*)(g_valh + rowbase + (size_t)row1 * DD + col) =
            packh2(accO[nf][2] * inv1, accO[nf][3] * inv1);
    }
}

// ---------------------------------------------------------------------------
extern "C" void kernel_launch(void* const* d_in, const int* in_sizes, int n_in,
                              void* d_out, int out_size)
{
    (void)in_sizes; (void)n_in; (void)out_size;
    const float* x  = (const float*)d_in[0];
    const float* Wq = (const float*)d_in[2];
    const float* bq = (const float*)d_in[3];
    const float* Wk = (const float*)d_in[4];
    const float* bk = (const float*)d_in[5];
    const float* Wv = (const float*)d_in[6];
    const float* bv = (const float*)d_in[7];
    const float* Wo = (const float*)d_in[8];
    const float* bo = (const float*)d_in[9];
    float* out = (float*)d_out;

    __half *pxh, *pvalh, *pwT;
    cudaGetSymbolAddress((void**)&pxh,   g_xh);
    cudaGetSymbolAddress((void**)&pvalh, g_valh);
    cudaGetSymbolAddress((void**)&pwT,   g_wT);

    const int smbytes_q = 3 * (GTM + 128) * 80;   // 46080
    const int smbytes_o = 3 * (OTM + 128) * 80;   // 38400
    cudaFuncSetAttribute(qkv_gemm_k, cudaFuncAttributeMaxDynamicSharedMemorySize, smbytes_q);
    cudaFuncSetAttribute(out_gemm_k, cudaFuncAttributeMaxDynamicSharedMemorySize, smbytes_o);

    // fp32->fp16 conversions (x + all 4 weight transposes, one launch)
    const int n8 = MTOT * DD / 8;
    conv_all_k<<<NCVH + 4096, 256>>>((const float4*)x, (uint4*)pxh, n8,
                                     Wq, Wk, Wv, Wo, pwT);

    // fused Q/K/V projections (TM=64 tiles -> 3072 CTAs)
    qkv_gemm_k<<<dim3(3 * DD / 128, MTOT / GTM), 256, smbytes_q>>>(pxh, pwT, bq, bk, bv);

    // linear attention (tensor-core passes, fp16 state)
    dim3 agrid(NCHUNK, NBH);
    kv_chunk_tc<<<agrid, 128>>>();
    prefix_k<<<NBH * 8, 256>>>();
    attn_out_tc<<<agrid, 128>>>();

    // output projection -> fp32 out (TM=32 tiles -> 2048 CTAs, 4 CTAs/SM)
    out_gemm_k<<<dim3(DD / 128, MTOT / OTM), 256, smbytes_o>>>(
        pvalh, pwT + 3 * (size_t)DD * DD, bo, out);
}

// round 16
// speedup vs baseline: 1.1912x; 1.1912x over previous
#include <cuda_runtime.h>
#include <cuda_fp16.h>
#include <cstdint>

// Problem constants (fixed by reference: B=4, S=2048, D=1024, H=16)
#define DD     1024
#define NH     16
#define HD     64
#define BATCH  4
#define SEQ    2048
#define MTOT   (BATCH * SEQ)      // 8192
#define CHUNK  64
#define NCHUNK (SEQ / CHUNK)      // 32
#define NBH    (BATCH * NH)       // 64
#define LDT    72                 // smem halves per tile row (64 + 8 pad)

// ---------------- scratch (allocation-free rule: __device__ globals) -------
__device__ __half g_KVh[NBH * NCHUNK * HD * HD];   // chunk KV -> exclusive prefix (fp16)
__device__ float  g_KS [NBH * NCHUNK * HD];

__device__ __half g_xh  [MTOT * DD];     // x in fp16
__device__ __half g_qh  [MTOT * DD];     // phi(xWq+b)
__device__ __half g_kh  [MTOT * DD];     // phi(xWk+b)
__device__ __half g_vh  [MTOT * DD];     // xWv+b
__device__ __half g_valh[MTOT * DD];     // attention output (fp16)
__device__ __half g_wT  [4][DD * DD];    // W^T fp16 (layout [N][K])

// ---------------------------------------------------------------------------
// PTX helpers (compute_100-safe: mma.sync / ldmatrix / cp.async only)
// ---------------------------------------------------------------------------
__device__ __forceinline__ uint32_t smem_u32(const void* p) {
    uint32_t a;
    asm("{ .reg .u64 t; cvta.to.shared.u64 t, %1; cvt.u32.u64 %0, t; }" : "=r"(a) : "l"(p));
    return a;
}

#define CP_ASYNC16(dst_u32, src_gptr) \
    asm volatile("cp.async.cg.shared.global [%0], [%1], 16;" \
                 :: "r"(dst_u32), "l"(src_gptr) : "memory")
#define CP_COMMIT() asm volatile("cp.async.commit_group;" ::: "memory")
#define CP_WAIT(n)  asm volatile("cp.async.wait_group %0;" :: "n"(n) : "memory")

#define LDSM_X4(r0, r1, r2, r3, addr) \
    asm volatile("ldmatrix.sync.aligned.m8n8.x4.shared.b16 {%0,%1,%2,%3}, [%4];" \
                 : "=r"(r0), "=r"(r1), "=r"(r2), "=r"(r3) : "r"(addr))

#define LDSM_X4_T(r0, r1, r2, r3, addr) \
    asm volatile("ldmatrix.sync.aligned.m8n8.x4.trans.shared.b16 {%0,%1,%2,%3}, [%4];" \
                 : "=r"(r0), "=r"(r1), "=r"(r2), "=r"(r3) : "r"(addr))

#define MMA16816F16(d, a, b0v, b1v) \
    asm volatile("mma.sync.aligned.m16n8k16.row.col.f32.f16.f16.f32 " \
                 "{%0,%1,%2,%3}, {%4,%5,%6,%7}, {%8,%9}, {%0,%1,%2,%3};" \
                 : "+f"((d)[0]), "+f"((d)[1]), "+f"((d)[2]), "+f"((d)[3]) \
                 : "r"((a)[0]), "r"((a)[1]), "r"((a)[2]), "r"((a)[3]), \
                   "r"(b0v), "r"(b1v))

__device__ __forceinline__ uint32_t packh2(float x, float y) {
    __half2 h = __floats2half2_rn(x, y);
    return *(uint32_t*)&h;
}

// ---------------------------------------------------------------------------
// Merged conversion kernel: blocks [0, NCVH) do x fp32->fp16; the rest do the
// four weight transposes+converts. One launch, both parts run concurrently.
// ---------------------------------------------------------------------------
#define NCVH 1184
__global__ __launch_bounds__(256)
void conv_all_k(const float4* __restrict__ x, uint4* __restrict__ xh, int n8,
                const float* __restrict__ W0, const float* __restrict__ W1,
                const float* __restrict__ W2, const float* __restrict__ W3,
                __half* __restrict__ hTbase)
{
    __shared__ float t[32][33];
    const int tid = threadIdx.x;
    if (blockIdx.x < NCVH) {
        for (int i = blockIdx.x * 256 + tid; i < n8; i += NCVH * 256) {
            float4 a = x[2 * i];
            float4 b = x[2 * i + 1];
            uint4 o;
            o.x = packh2(a.x, a.y);
            o.y = packh2(a.z, a.w);
            o.z = packh2(b.x, b.y);
            o.w = packh2(b.z, b.w);
            xh[i] = o;
        }
    } else {
        const int bidx = blockIdx.x - NCVH;        // 0..4095
        const int z = bidx >> 10;
        const int rem = bidx & 1023;
        const int n0 = (rem & 31) * 32, k0 = (rem >> 5) * 32;
        const float* W = (z == 0) ? W0 : (z == 1) ? W1 : (z == 2) ? W2 : W3;
        __half* hT = hTbase + (size_t)z * DD * DD;
        const int tx = tid & 31, ty = tid >> 5;    // 32 x 8
        #pragma unroll
        for (int r = ty; r < 32; r += 8)
            t[r][tx] = W[(size_t)(k0 + r) * DD + n0 + tx];
        __syncthreads();
        #pragma unroll
        for (int r = ty; r < 32; r += 8)
            hT[(size_t)(n0 + r) * DD + k0 + tx] = __float2half_rn(t[tx][r]);
    }
}

// ---------------------------------------------------------------------------
// fp16 tensor-core GEMM mainloop body
// CTA tile TM x 128, BK=32, 8 warps (warp tile (TM/2) x 32), 3-stage cp.async,
// single __syncthreads per k-iteration, 3 CTAs/SM at TM=64.
// ---------------------------------------------------------------------------
template<int HALF_OUT, int TM>
__device__ __forceinline__
void gemm_body(int tid, uint32_t sb, uint64_t gA, uint64_t gB,
               int m0, int n0, bool act, const float* bias, void* Cg)
{
    constexpr int SROWB  = 80;
    constexpr int ATILEB = TM * SROWB;
    constexpr int BTILEB = 128 * SROWB;
    constexpr int STAGEB = ATILEB + BTILEB;
    constexpr int NIT    = DD / 32;
    constexpr int MF     = TM / 32;          // m16-fragments per warp

    const int lane = tid & 31;
    const int wid = tid >> 5;
    const int wm = wid & 1;                  // M half
    const int wn = wid >> 1;                 // 32-col slab
    const uint32_t aOff = (uint32_t)(wm * (TM / 2) + (lane & 15)) * SROWB
                        + (uint32_t)(lane >> 4) * 16;
    const uint32_t bOff = (uint32_t)(wn * 32 + (lane & 7) + ((lane >> 4) << 3)) * SROWB
                        + (uint32_t)((lane >> 3) & 1) * 16;

    float acc[MF][4][4];
    #pragma unroll
    for (int i = 0; i < MF; i++)
        #pragma unroll
        for (int j = 0; j < 4; j++)
            #pragma unroll
            for (int q = 0; q < 4; q++) acc[i][j][q] = 0.f;

    auto load_stage = [&](int slot, int kc) {
        const uint32_t sbase = sb + slot * STAGEB;
        #pragma unroll
        for (int j = 0; j < TM * 4 / 256; j++) {     // A: TM rows x 4 chunks
            const int idx = tid + 256 * j;
            const int row = idx >> 2, k = idx & 3;
            CP_ASYNC16(sbase + row * SROWB + k * 16,
                       gA + ((size_t)(m0 + row) * DD + kc + k * 8) * 2);
        }
        #pragma unroll
        for (int j = 0; j < 2; j++) {                // B: 128 rows x 4 chunks
            const int idx = tid + 256 * j;
            const int row = idx >> 2, k = idx & 3;
            CP_ASYNC16(sbase + ATILEB + row * SROWB + k * 16,
                       gB + ((size_t)(n0 + row) * DD + kc + k * 8) * 2);
        }
    };

    load_stage(0, 0);  CP_COMMIT();
    load_stage(1, 32); CP_COMMIT();

    for (int it = 0; it < NIT; it++) {
        if (it + 1 < NIT) { CP_WAIT(1); } else { CP_WAIT(0); }
        __syncthreads();
        if (it + 2 < NIT) { load_stage((it + 2) % 3, (it + 2) * 32); CP_COMMIT(); }

        const int slot = it % 3;
        const uint32_t sA = sb + slot * STAGEB;
        const uint32_t sB = sA + ATILEB;

        #pragma unroll
        for (int k16 = 0; k16 < 2; k16++) {
            const uint32_t kb = k16 * 32;
            uint32_t ah[MF][4];
            #pragma unroll
            for (int mf = 0; mf < MF; mf++) {
                const uint32_t ao = aOff + mf * 16 * SROWB + kb;
                LDSM_X4(ah[mf][0], ah[mf][1], ah[mf][2], ah[mf][3], sA + ao);
            }
            uint32_t bb[2][4];
            #pragma unroll
            for (int gg = 0; gg < 2; gg++) {
                const uint32_t bo = bOff + gg * 16 * SROWB + kb;
                LDSM_X4(bb[gg][0], bb[gg][1], bb[gg][2], bb[gg][3], sB + bo);
            }
            #pragma unroll
            for (int mf = 0; mf < MF; mf++) {
                #pragma unroll
                for (int nf = 0; nf < 4; nf++) {
                    const int gg = nf >> 1, p = (nf & 1) * 2;
                    MMA16816F16(acc[mf][nf], ah[mf], bb[gg][p], bb[gg][p + 1]);
                }
            }
        }
    }

    #pragma unroll
    for (int nf = 0; nf < 4; nf++) {
        const int cg = n0 + wn * 32 + nf * 8 + (lane & 3) * 2;
        const float b0 = __ldg(&bias[cg]);
        const float b1 = __ldg(&bias[cg + 1]);
        #pragma unroll
        for (int mf = 0; mf < MF; mf++) {
            const int rg = m0 + wm * (TM / 2) + mf * 16 + (lane >> 2);
            float v0 = acc[mf][nf][0] + b0;
            float v1 = acc[mf][nf][1] + b1;
            float v2 = acc[mf][nf][2] + b0;
            float v3 = acc[mf][nf][3] + b1;
            if (act) {
                v0 = (v0 > 0.f) ? (v0 + 1.f) : __expf(v0);
                v1 = (v1 > 0.f) ? (v1 + 1.f) : __expf(v1);
                v2 = (v2 > 0.f) ? (v2 + 1.f) : __expf(v2);
                v3 = (v3 > 0.f) ? (v3 + 1.f) : __expf(v3);
            }
            if (HALF_OUT) {
                __half* Ch = (__half*)Cg;
                *(__half2*)(Ch + (size_t)rg * DD + cg)       = __floats2half2_rn(v0, v1);
                *(__half2*)(Ch + (size_t)(rg + 8) * DD + cg) = __floats2half2_rn(v2, v3);
            } else {
                float* Cf = (float*)Cg;
                *(float2*)(Cf + (size_t)rg * DD + cg)       = make_float2(v0, v1);
                *(float2*)(Cf + (size_t)(rg + 8) * DD + cg) = make_float2(v2, v3);
            }
        }
    }
}

#define GTM 64   // GEMM M-tile (both projections)

// Fused Q/K/V projections: grid.x = 3*8 (which*8 + nblk), grid.y = MTOT/GTM
__global__ __launch_bounds__(256, 3)
void qkv_gemm_k(const __half* __restrict__ A, const __half* __restrict__ wT,
                const float* __restrict__ bq, const float* __restrict__ bk,
                const float* __restrict__ bv)
{
    extern __shared__ char smem[];
    const int which = blockIdx.x >> 3;
    const int n0 = (blockIdx.x & 7) * 128;
    const int m0 = blockIdx.y * GTM;
    const __half* BT = wT + (size_t)which * DD * DD;
    const float* bias = (which == 0) ? bq : (which == 1) ? bk : bv;
    __half* out = (which == 0) ? g_qh : (which == 1) ? g_kh : g_vh;
    gemm_body<1, GTM>(threadIdx.x, smem_u32(smem), __cvta_generic_to_global(A),
                      __cvta_generic_to_global(BT), m0, n0, which < 2, bias, out);
}

// Output projection: fp16 A, fp32 C
__global__ __launch_bounds__(256, 3)
void out_gemm_k(const __half* __restrict__ A, const __half* __restrict__ BT,
                const float* __restrict__ bias, float* __restrict__ Cg)
{
    extern __shared__ char smem[];
    gemm_body<0, GTM>(threadIdx.x, smem_u32(smem), __cvta_generic_to_global(A),
                      __cvta_generic_to_global(BT), blockIdx.y * GTM,
                      blockIdx.x * 128, false, bias, Cg);
}

// ---------------------------------------------------------------------------
// Async tile loaders: 64x64 fp16 -> smem [64][LDT] via cp.async
// ---------------------------------------------------------------------------
__device__ __forceinline__
void load_tile_cp(uint32_t dst_s, const __half* src, size_t rowbase, int tid)
{
    #pragma unroll
    for (int j = 0; j < 4; j++) {
        const int idx = tid + 128 * j;
        const int row = idx >> 3;
        const int c = (idx & 7) * 8;
        CP_ASYNC16(dst_s + (uint32_t)(row * LDT + c) * 2,
                   (const void*)(src + rowbase + (size_t)row * DD + c));
    }
}
__device__ __forceinline__
void load_tile_cp_s(uint32_t dst_s, const __half* src, int tid)
{
    #pragma unroll
    for (int j = 0; j < 4; j++) {
        const int idx = tid + 128 * j;
        const int row = idx >> 3;
        const int c = (idx & 7) * 8;
        CP_ASYNC16(dst_s + (uint32_t)(row * LDT + c) * 2,
                   (const void*)(src + (size_t)row * HD + c));
    }
}

// ---------------------------------------------------------------------------
// Pass A (tensor core): KV_c[d][m] = sum_t K[t][d] V[t][m] (fp16 out);
// ks_c[d] = sum_t K[t][d] (fp32)
// ---------------------------------------------------------------------------
__global__ __launch_bounds__(128)
void kv_chunk_tc()
{
    __shared__ __half Ks[CHUNK][LDT];
    __shared__ __half Vs[CHUNK][LDT];

    const int c = blockIdx.x, bh = blockIdx.y;
    const int b = bh >> 4, h = bh & 15;
    const int tid = threadIdx.x;
    const int w = tid >> 5, l = tid & 31;
    const size_t rowbase = (size_t)(b * SEQ + c * CHUNK) * DD + h * HD;

    load_tile_cp(smem_u32(Ks), g_kh, rowbase, tid);
    load_tile_cp(smem_u32(Vs), g_vh, rowbase, tid);
    CP_COMMIT();
    CP_WAIT(0);
    __syncthreads();

    const int tRow = ((l >> 4) << 3) + (l & 7);
    const int tColA = ((l >> 3) & 1) * 8;
    const int tRowB = ((l >> 3) & 1) * 8 + (l & 7);
    const int tColB = (l >> 4) * 8;

    float acc[8][4];
    #pragma unroll
    for (int i = 0; i < 8; i++)
        #pragma unroll
        for (int q = 0; q < 4; q++) acc[i][q] = 0.f;

    #pragma unroll
    for (int kk = 0; kk < 4; kk++) {
        uint32_t a[4];
        LDSM_X4_T(a[0], a[1], a[2], a[3],
                  smem_u32(&Ks[kk * 16 + tRow][w * 16 + tColA]));
        #pragma unroll
        for (int gN = 0; gN < 4; gN++) {
            uint32_t r0, r1, r2, r3;
            LDSM_X4_T(r0, r1, r2, r3,
                      smem_u32(&Vs[kk * 16 + tRowB][gN * 16 + tColB]));
            MMA16816F16(acc[2 * gN],     a, r0, r1);
            MMA16816F16(acc[2 * gN + 1], a, r2, r3);
        }
    }

    __half* outp = g_KVh + (size_t)(bh * NCHUNK + c) * HD * HD;
    const int r0 = w * 16 + (l >> 2);
    #pragma unroll
    for (int nf = 0; nf < 8; nf++) {
        const int col = nf * 8 + 2 * (l & 3);
        *(uint32_t*)(outp + (size_t)r0 * HD + col)       = packh2(acc[nf][0], acc[nf][1]);
        *(uint32_t*)(outp + (size_t)(r0 + 8) * HD + col) = packh2(acc[nf][2], acc[nf][3]);
    }

    if (tid < HD) {
        float s = 0.f;
        #pragma unroll 8
        for (int t = 0; t < CHUNK; t++) s += __half2float(Ks[t][tid]);
        g_KS[(bh * NCHUNK + c) * HD + tid] = s;
    }
}

// ---------------------------------------------------------------------------
// Pass B: in-place EXCLUSIVE prefix over chunks. 8 CTAs per bh; each thread
// owns one half2 lane. All 32 chunk values preloaded into registers (MLP=32),
// scan in registers, then store.
// ---------------------------------------------------------------------------
__global__ __launch_bounds__(256)
void prefix_k()
{
    const int bh = blockIdx.x >> 3;
    const int pos = (blockIdx.x & 7) * 256 + threadIdx.x;   // 0..2047 half2 lanes
    __half* base = g_KVh + (size_t)bh * NCHUNK * HD * HD + pos * 2;

    uint32_t v[NCHUNK];
    #pragma unroll
    for (int c = 0; c < NCHUNK; c++)
        v[c] = *(const uint32_t*)(base + (size_t)c * HD * HD);

    float rx = 0.f, ry = 0.f;
    #pragma unroll
    for (int c = 0; c < NCHUNK; c++) {
        float2 f = __half22float2(*(__half2*)&v[c]);
        *(uint32_t*)(base + (size_t)c * HD * HD) = packh2(rx, ry);
        rx += f.x; ry += f.y;
    }

    if ((blockIdx.x & 7) == 0 && threadIdx.x < HD) {
        float* zb = g_KS + (size_t)bh * NCHUNK * HD + threadIdx.x;
        float zv[NCHUNK];
        #pragma unroll
        for (int c = 0; c < NCHUNK; c++) zv[c] = zb[(size_t)c * HD];
        float r = 0.f;
        #pragma unroll
        for (int c = 0; c < NCHUNK; c++) {
            zb[(size_t)c * HD] = r;
            r += zv[c];
        }
    }
}

// ---------------------------------------------------------------------------
// Pass C (tensor core): out = (tril(QK^T) V + Q S_prev) / (rowsum + Q.z + eps)
// K and V share one smem buffer (K dead after Phase 1) -> 28.5 KB, 8 CTAs/SM.
// ---------------------------------------------------------------------------
__global__ __launch_bounds__(128)
void attn_out_tc()
{
    __shared__ __half Qs [CHUNK][LDT];
    __shared__ __half KVs[CHUNK][LDT];     // K in Phase 1, V in Phase 2
    __shared__ __half Sph[HD][LDT];
    __shared__ float rs[CHUNK], den[CHUNK], zp[HD];

    const int c = blockIdx.x, bh = blockIdx.y;
    const int b = bh >> 4, h = bh & 15;
    const int tid = threadIdx.x;
    const int w = tid >> 5, l = tid & 31;
    const size_t rowbase = (size_t)(b * SEQ + c * CHUNK) * DD + h * HD;
    const __half* Sp = g_KVh + (size_t)(bh * NCHUNK + c) * HD * HD;

    load_tile_cp(smem_u32(Qs), g_qh, rowbase, tid);
    load_tile_cp(smem_u32(KVs), g_kh, rowbase, tid);
    load_tile_cp_s(smem_u32(Sph), Sp, tid);
    CP_COMMIT();
    if (tid < HD) zp[tid] = g_KS[(bh * NCHUNK + c) * HD + tid];
    CP_WAIT(0);
    __syncthreads();

    const uint32_t aRow = w * 16 + (l & 15);
    const uint32_t aK = (l >> 4) * 8;
    const uint32_t bRow = (l & 7) + ((l >> 4) << 3);
    const uint32_t bK = ((l >> 3) & 1) * 8;
    const int tRowB = ((l >> 3) & 1) * 8 + (l & 7);
    const int tColB = (l >> 4) * 8;

    // Phase 1: S = Q K^T
    float accS[8][4];
    #pragma unroll
    for (int i = 0; i < 8; i++)
        #pragma unroll
        for (int q = 0; q < 4; q++) accS[i][q] = 0.f;

    #pragma unroll
    for (int kk = 0; kk < 4; kk++) {
        uint32_t a[4];
        LDSM_X4(a[0], a[1], a[2], a[3], smem_u32(&Qs[aRow][kk * 16 + aK]));
        #pragma unroll
        for (int gN = 0; gN < 4; gN++) {
            uint32_t r0, r1, r2, r3;
            LDSM_X4(r0, r1, r2, r3, smem_u32(&KVs[gN * 16 + bRow][kk * 16 + bK]));
            MMA16816F16(accS[2 * gN],     a, r0, r1);
            MMA16816F16(accS[2 * gN + 1], a, r2, r3);
        }
    }

    const int row0 = w * 16 + (l >> 2);
    const int row1 = row0 + 8;
    float sum0 = 0.f, sum1 = 0.f;
    #pragma unroll
    for (int nf = 0; nf < 8; nf++) {
        #pragma unroll
        for (int jj = 0; jj < 2; jj++) {
            const int col = nf * 8 + 2 * (l & 3) + jj;
            accS[nf][jj]     = (col <= row0) ? accS[nf][jj]     : 0.f;
            accS[nf][2 + jj] = (col <= row1) ? accS[nf][2 + jj] : 0.f;
            sum0 += accS[nf][jj];
            sum1 += accS[nf][2 + jj];
        }
    }
    sum0 += __shfl_xor_sync(0xFFFFFFFF, sum0, 1);
    sum0 += __shfl_xor_sync(0xFFFFFFFF, sum0, 2);
    sum1 += __shfl_xor_sync(0xFFFFFFFF, sum1, 1);
    sum1 += __shfl_xor_sync(0xFFFFFFFF, sum1, 2);
    if ((l & 3) == 0) { rs[row0] = sum0; rs[row1] = sum1; }
    __syncthreads();   // all warps done with K reads + rs visible

    // reload KVs with V while computing denominators
    load_tile_cp(smem_u32(KVs), g_vh, rowbase, tid);
    CP_COMMIT();
    if (tid < CHUNK) {
        float qz = 0.f;
        #pragma unroll 8
        for (int d = 0; d < HD; d++) qz = fmaf(__half2float(Qs[tid][d]), zp[d], qz);
        den[tid] = rs[tid] + qz + 1e-6f;
    }
    CP_WAIT(0);
    __syncthreads();

    // Phase 2: O = S V + Q S_prev
    float accO[8][4];
    #pragma unroll
    for (int i = 0; i < 8; i++)
        #pragma unroll
        for (int q = 0; q < 4; q++) accO[i][q] = 0.f;

    #pragma unroll
    for (int kk = 0; kk < 4; kk++) {
        uint32_t a[4];
        a[0] = packh2(accS[2 * kk][0],     accS[2 * kk][1]);
        a[1] = packh2(accS[2 * kk][2],     accS[2 * kk][3]);
        a[2] = packh2(accS[2 * kk + 1][0], accS[2 * kk + 1][1]);
        a[3] = packh2(accS[2 * kk + 1][2], accS[2 * kk + 1][3]);
        #pragma unroll
        for (int gN = 0; gN < 4; gN++) {
            uint32_t r0, r1, r2, r3;
            LDSM_X4_T(r0, r1, r2, r3,
                      smem_u32(&KVs[kk * 16 + tRowB][gN * 16 + tColB]));
            MMA16816F16(accO[2 * gN],     a, r0, r1);
            MMA16816F16(accO[2 * gN + 1], a, r2, r3);
        }
    }
    #pragma unroll
    for (int kk = 0; kk < 4; kk++) {
        uint32_t a[4];
        LDSM_X4(a[0], a[1], a[2], a[3], smem_u32(&Qs[aRow][kk * 16 + aK]));
        #pragma unroll
        for (int gN = 0; gN < 4; gN++) {
            uint32_t r0, r1, r2, r3;
            LDSM_X4_T(r0, r1, r2, r3,
                      smem_u32(&Sph[kk * 16 + tRowB][gN * 16 + tColB]));
            MMA16816F16(accO[2 * gN],     a, r0, r1);
            MMA16816F16(accO[2 * gN + 1], a, r2, r3);
        }
    }

    const float inv0 = 1.0f / den[row0];
    const float inv1 = 1.0f / den[row1];
    #pragma unroll
    for (int nf = 0; nf < 8; nf++) {
        const int col = nf * 8 + 2 * (l & 3);
        *(uint32_t*)(g_valh + rowbase + (size_t)row0 * DD + col) =
            packh2(accO[nf][0] * inv0, accO[nf][1] * inv0);
        *(uint32_t*)(g_valh + rowbase + (size_t)row1 * DD + col) =
            packh2(accO[nf][2] * inv1, accO[nf][3] * inv1);
    }
}

// ---------------------------------------------------------------------------
extern "C" void kernel_launch(void* const* d_in, const int* in_sizes, int n_in,
                              void* d_out, int out_size)
{
    (void)in_sizes; (void)n_in; (void)out_size;
    const float* x  = (const float*)d_in[0];
    const float* Wq = (const float*)d_in[2];
    const float* bq = (const float*)d_in[3];
    const float* Wk = (const float*)d_in[4];
    const float* bk = (const float*)d_in[5];
    const float* Wv = (const float*)d_in[6];
    const float* bv = (const float*)d_in[7];
    const float* Wo = (const float*)d_in[8];
    const float* bo = (const float*)d_in[9];
    float* out = (float*)d_out;

    __half *pxh, *pvalh, *pwT;
    cudaGetSymbolAddress((void**)&pxh,   g_xh);
    cudaGetSymbolAddress((void**)&pvalh, g_valh);
    cudaGetSymbolAddress((void**)&pwT,   g_wT);

    const int smbytes_g = 3 * (GTM + 128) * 80;   // 46080 (3 stages x (A+B))
    cudaFuncSetAttribute(qkv_gemm_k, cudaFuncAttributeMaxDynamicSharedMemorySize, smbytes_g);
    cudaFuncSetAttribute(out_gemm_k, cudaFuncAttributeMaxDynamicSharedMemorySize, smbytes_g);

    // fp32->fp16 conversions (x + all 4 weight transposes, one launch)
    const int n8 = MTOT * DD / 8;
    conv_all_k<<<NCVH + 4096, 256>>>((const float4*)x, (uint4*)pxh, n8,
                                     Wq, Wk, Wv, Wo, pwT);

    // fused Q/K/V projections (TM=64 tiles -> 3072 CTAs)
    qkv_gemm_k<<<dim3(3 * DD / 128, MTOT / GTM), 256, smbytes_g>>>(pxh, pwT, bq, bk, bv);

    // linear attention (tensor-core passes, fp16 state)
    dim3 agrid(NCHUNK, NBH);
    kv_chunk_tc<<<agrid, 128>>>();
    prefix_k<<<NBH * 8, 256>>>();
    attn_out_tc<<<agrid, 128>>>();

    // output projection -> fp32 out (TM=64 tiles -> 1024 CTAs)
    out_gemm_k<<<dim3(DD / 128, MTOT / GTM), 256, smbytes_g>>>(
        pvalh, pwT + 3 * (size_t)DD * DD, bo, out);
}